// round 16
// baseline (speedup 1.0000x reference)
#include <cuda_runtime.h>
#include <cuda_pipeline.h>

// x [8, 65536, 256] fp32 -> per-sample classical Gram-Schmidt over 8 vectors.
// R13: R8 per-warp structure (SPW=4, single 8KB staging buffer/warp, cp.async
// prefetch right after the smem->reg drain, Cholesky formulation = exact
// classical GS), with 256-thread blocks (8 warps) so each block covers 8
// CONSECUTIVE samples -> every per-iteration model-row access is an 8KB
// contiguous DRAM burst (vs 4KB in R8), targeting HBM R/W-turnaround and
// row-activate overhead — the hypothesized source of the stable 82% plateau.
// Occupancy unchanged: 2 CTAs x 8 warps = 16 warps/SM (reg-bound, 128 regs).
// 64KB smem/block -> dynamic smem + cudaFuncSetAttribute (idempotent,
// capture-safe host call).

#define NSAMP 65536
#define NDIM  256
#define NMOD  8
#define WPB   8                    // warps per block
#define SPW   4                    // samples per warp
#define TOTAL_WARPS (NSAMP / SPW)  // 16384
#define SMEM_BYTES (WPB * NMOD * 2 * 32 * 16)  // 65536
#define TRI(i, j) ((i) * ((i) + 1) / 2 + (j))

__device__ __forceinline__ float warp_sum(float v) {
#pragma unroll
    for (int o = 16; o; o >>= 1)
        v += __shfl_xor_sync(0xffffffffu, v, o);
    return v;
}

__device__ __forceinline__ float dot8(const float4& p0, const float4& p1,
                                      const float4& q0, const float4& q1) {
    return p0.x * q0.x + p0.y * q0.y + p0.z * q0.z + p0.w * q0.w
         + p1.x * q1.x + p1.y * q1.y + p1.z * q1.z + p1.w * q1.w;
}

__device__ __forceinline__ void prefetch_sample(
    float4 (*buf)[2][32], const float* __restrict__ x,
    size_t samp, int lane) {
    const size_t model_stride = (size_t)NSAMP * NDIM;
    const float* p = x + samp * NDIM;
#pragma unroll
    for (int i = 0; i < NMOD; i++) {
        const float* v = p + i * model_stride;
        __pipeline_memcpy_async(&buf[i][0][lane], v + 4 * lane, 16);
        __pipeline_memcpy_async(&buf[i][1][lane], v + 128 + 4 * lane, 16);
    }
}

__global__ __launch_bounds__(256, 2)
void gram_schmidt_kernel(const float* __restrict__ x, float* __restrict__ out) {
    const int wib  = threadIdx.x >> 5;
    const int lane = threadIdx.x & 31;
    // Consecutive warps in a block = consecutive samples -> the block's 8
    // warps read/write 8KB-contiguous spans of every model row per iteration.
    const int gwarp = blockIdx.x * WPB + wib;

    extern __shared__ float4 sbuf[];
    float4 (*mybuf)[2][32] =
        reinterpret_cast<float4(*)[2][32]>(sbuf + (size_t)wib * (NMOD * 2 * 32));

    const size_t model_stride = (size_t)NSAMP * NDIM;
    const int d0 = 4 * lane;
    const int d1 = 128 + 4 * lane;

    // Prologue: stage sample 0.
    prefetch_sample(mybuf, x, (size_t)gwarp, lane);
    __pipeline_commit();

    for (int it = 0; it < SPW; it++) {
        const size_t samp = (size_t)gwarp + (size_t)it * TOTAL_WARPS;
        const size_t samp_off = samp * NDIM;

        // Wait for this sample's staged data, pull into registers.
        __pipeline_wait_prior(0);
        float4 a[NMOD][2];
#pragma unroll
        for (int i = 0; i < NMOD; i++) {
            a[i][0] = mybuf[i][0][lane];
            a[i][1] = mybuf[i][1][lane];
        }

        // Buffer fully drained into registers -> issue the next sample's
        // DRAM->smem stream NOW; it overlaps the whole compute phase.
        // (cp.async smem writes land at data-return time — no WAR hazard.)
        if (it + 1 < SPW)
            prefetch_sample(mybuf, x, (size_t)gwarp + (size_t)(it + 1) * TOTAL_WARPS, lane);
        __pipeline_commit();

        // Gram matrix lower triangle: 36 independent warp reductions.
        float L[TRI(NMOD - 1, NMOD - 1) + 1];
#pragma unroll
        for (int i = 0; i < NMOD; i++)
#pragma unroll
            for (int j = 0; j <= i; j++)
                L[TRI(i, j)] = warp_sum(dot8(a[i][0], a[i][1], a[j][0], a[j][1]));

        // In-register 8x8 Cholesky G = L L^T (replicated per lane).
        float invd[NMOD];
#pragma unroll
        for (int i = 0; i < NMOD; i++) {
#pragma unroll
            for (int j = 0; j <= i; j++) {
                float s = L[TRI(i, j)];
#pragma unroll
                for (int m = 0; m < NMOD; m++)
                    if (m < j) s -= L[TRI(i, m)] * L[TRI(j, m)];
                if (j == i) {
                    invd[i] = rsqrtf(s);
                    L[TRI(i, i)] = s * invd[i];
                } else {
                    L[TRI(i, j)] = s * invd[j];  // = <v_i, b_j>
                }
            }
        }

        // Forward substitution: b_i = (v_i - sum_{j<i} L_ij b_j) * invd[i].
#pragma unroll
        for (int i = 0; i < NMOD; i++) {
#pragma unroll
            for (int j = 0; j < NMOD; j++) {
                if (j < i) {
                    const float c = L[TRI(i, j)];
                    a[i][0].x -= c * a[j][0].x;
                    a[i][0].y -= c * a[j][0].y;
                    a[i][0].z -= c * a[j][0].z;
                    a[i][0].w -= c * a[j][0].w;
                    a[i][1].x -= c * a[j][1].x;
                    a[i][1].y -= c * a[j][1].y;
                    a[i][1].z -= c * a[j][1].z;
                    a[i][1].w -= c * a[j][1].w;
                }
            }
            const float inv = invd[i];
            a[i][0].x *= inv; a[i][0].y *= inv; a[i][0].z *= inv; a[i][0].w *= inv;
            a[i][1].x *= inv; a[i][1].y *= inv; a[i][1].z *= inv; a[i][1].w *= inv;

            float* q = out + (size_t)i * model_stride + samp_off;
            __stcs(reinterpret_cast<float4*>(q + d0), a[i][0]);
            __stcs(reinterpret_cast<float4*>(q + d1), a[i][1]);
        }
    }
}

extern "C" void kernel_launch(void* const* d_in, const int* in_sizes, int n_in,
                              void* d_out, int out_size) {
    const float* x = (const float*)d_in[0];
    float* out = (float*)d_out;
    // Idempotent, capture-safe (not a stream operation).
    cudaFuncSetAttribute(gram_schmidt_kernel,
                         cudaFuncAttributeMaxDynamicSharedMemorySize, SMEM_BYTES);
    // 16384 warps x 4 samples; 8 warps (256 threads) per block -> 2048 blocks.
    gram_schmidt_kernel<<<TOTAL_WARPS / WPB, 256, SMEM_BYTES>>>(x, out);
}

// round 17
// speedup vs baseline: 1.0990x; 1.0990x over previous
#include <cuda_runtime.h>
#include <cuda_pipeline.h>

// x [8, 65536, 256] fp32 -> per-sample classical Gram-Schmidt over 8 vectors.
// FINAL (= R8 config; best measured across 3 reproductions: 161.0-161.6us
// bench, 155.1-156.5us ncu, DRAM 82.0-82.8%, rel_err 9.2e-8).
//
// Structure:
//  - 1 warp per sample slot; 128-thr blocks (4 warps), SPW=4 samples/warp,
//    4096 blocks. STATIC smem buffer (compile-time addressing matters: the
//    dynamic-smem variant R13 inflated issue pressure and regressed to 176us;
//    persistent-grid R11 regressed to 188us; multi-wave grid load-balances).
//  - cp.async (LDGSTS) stages the next sample's 8KB DRAM->smem while the
//    current sample computes from registers; prefetch issued immediately
//    after the smem->reg drain (no WAR hazard: cp.async smem writes land at
//    data-return time, long after the LDS drain completes).
//  - Math: G = X X^T (36 independent warp-shuffle reductions, one reduction
//    depth), in-register 8x8 Cholesky G = L L^T, forward substitution
//    b_i = (v_i - sum_{j<i} L_ij b_j)/L_ii -- algebraically exact classical
//    Gram-Schmidt (L_ij = <v_i, b_j>).
//
// Roofline: 10 structural variants plateau at <=82.8% DRAM ~6.55 TB/s with
// traffic at the 1.014 GB theoretical minimum and LTS well under its cap ->
// bound by HBM 1:1 read:write-mix efficiency. This config is the fastest.

#define NSAMP 65536
#define NDIM  256
#define NMOD  8
#define WPB   4                    // warps per block
#define SPW   4                    // samples per warp
#define TOTAL_WARPS (NSAMP / SPW)  // 16384
#define TRI(i, j) ((i) * ((i) + 1) / 2 + (j))

__device__ __forceinline__ float warp_sum(float v) {
#pragma unroll
    for (int o = 16; o; o >>= 1)
        v += __shfl_xor_sync(0xffffffffu, v, o);
    return v;
}

__device__ __forceinline__ float dot8(const float4& p0, const float4& p1,
                                      const float4& q0, const float4& q1) {
    return p0.x * q0.x + p0.y * q0.y + p0.z * q0.z + p0.w * q0.w
         + p1.x * q1.x + p1.y * q1.y + p1.z * q1.z + p1.w * q1.w;
}

__device__ __forceinline__ void prefetch_sample(
    float4 (*buf)[2][32], const float* __restrict__ x,
    size_t samp, int lane) {
    const size_t model_stride = (size_t)NSAMP * NDIM;
    const float* p = x + samp * NDIM;
#pragma unroll
    for (int i = 0; i < NMOD; i++) {
        const float* v = p + i * model_stride;
        __pipeline_memcpy_async(&buf[i][0][lane], v + 4 * lane, 16);
        __pipeline_memcpy_async(&buf[i][1][lane], v + 128 + 4 * lane, 16);
    }
}

__global__ __launch_bounds__(128, 4)
void gram_schmidt_kernel(const float* __restrict__ x, float* __restrict__ out) {
    const int wib  = threadIdx.x >> 5;
    const int lane = threadIdx.x & 31;
    const int gwarp = blockIdx.x * WPB + wib;

    // 8 KB staging buffer per warp (one sample), 32 KB static per block.
    __shared__ float4 buf[WPB][NMOD][2][32];
    float4 (*mybuf)[2][32] = buf[wib];

    const size_t model_stride = (size_t)NSAMP * NDIM;
    const int d0 = 4 * lane;
    const int d1 = 128 + 4 * lane;

    // Prologue: stage sample 0.
    prefetch_sample(mybuf, x, (size_t)gwarp, lane);
    __pipeline_commit();

    for (int it = 0; it < SPW; it++) {
        const size_t samp = (size_t)gwarp + (size_t)it * TOTAL_WARPS;
        const size_t samp_off = samp * NDIM;

        // Wait for this sample's staged data, pull into registers.
        __pipeline_wait_prior(0);
        float4 a[NMOD][2];
#pragma unroll
        for (int i = 0; i < NMOD; i++) {
            a[i][0] = mybuf[i][0][lane];
            a[i][1] = mybuf[i][1][lane];
        }

        // Buffer fully drained into registers -> issue the next sample's
        // DRAM->smem stream NOW; it overlaps the whole compute phase.
        if (it + 1 < SPW)
            prefetch_sample(mybuf, x, (size_t)gwarp + (size_t)(it + 1) * TOTAL_WARPS, lane);
        __pipeline_commit();

        // Gram matrix lower triangle: 36 independent warp reductions.
        float L[TRI(NMOD - 1, NMOD - 1) + 1];
#pragma unroll
        for (int i = 0; i < NMOD; i++)
#pragma unroll
            for (int j = 0; j <= i; j++)
                L[TRI(i, j)] = warp_sum(dot8(a[i][0], a[i][1], a[j][0], a[j][1]));

        // In-register 8x8 Cholesky G = L L^T (replicated per lane).
        float invd[NMOD];
#pragma unroll
        for (int i = 0; i < NMOD; i++) {
#pragma unroll
            for (int j = 0; j <= i; j++) {
                float s = L[TRI(i, j)];
#pragma unroll
                for (int m = 0; m < NMOD; m++)
                    if (m < j) s -= L[TRI(i, m)] * L[TRI(j, m)];
                if (j == i) {
                    invd[i] = rsqrtf(s);
                    L[TRI(i, i)] = s * invd[i];
                } else {
                    L[TRI(i, j)] = s * invd[j];  // = <v_i, b_j>
                }
            }
        }

        // Forward substitution: b_i = (v_i - sum_{j<i} L_ij b_j) * invd[i].
#pragma unroll
        for (int i = 0; i < NMOD; i++) {
#pragma unroll
            for (int j = 0; j < NMOD; j++) {
                if (j < i) {
                    const float c = L[TRI(i, j)];
                    a[i][0].x -= c * a[j][0].x;
                    a[i][0].y -= c * a[j][0].y;
                    a[i][0].z -= c * a[j][0].z;
                    a[i][0].w -= c * a[j][0].w;
                    a[i][1].x -= c * a[j][1].x;
                    a[i][1].y -= c * a[j][1].y;
                    a[i][1].z -= c * a[j][1].z;
                    a[i][1].w -= c * a[j][1].w;
                }
            }
            const float inv = invd[i];
            a[i][0].x *= inv; a[i][0].y *= inv; a[i][0].z *= inv; a[i][0].w *= inv;
            a[i][1].x *= inv; a[i][1].y *= inv; a[i][1].z *= inv; a[i][1].w *= inv;

            float* q = out + (size_t)i * model_stride + samp_off;
            __stcs(reinterpret_cast<float4*>(q + d0), a[i][0]);
            __stcs(reinterpret_cast<float4*>(q + d1), a[i][1]);
        }
    }
}

extern "C" void kernel_launch(void* const* d_in, const int* in_sizes, int n_in,
                              void* d_out, int out_size) {
    const float* x = (const float*)d_in[0];
    float* out = (float*)d_out;
    // 16384 warps x 4 samples; 4 warps (128 threads) per block -> 4096 blocks.
    gram_schmidt_kernel<<<TOTAL_WARPS / WPB, 128>>>(x, out);
}